// round 15
// baseline (speedup 1.0000x reference)
#include <cuda_runtime.h>
#include <cuda_fp16.h>
#include <math.h>
#include <stdint.h>

// ---------------------------------------------------------------------------
// AFNO2D: out = x + fuse_w @ (x + irfft2(D)),   D = masked_MLP(Z) - Z on the
// 64x33 low-frequency region of Z = rfft2(x, ortho).
// HMMA fp16 single-precision in the frequency path.  Z/D packed half2,
// channel-major.  k_fwd emits fp16 x (g_xh); k_inv epilogue is staged +
// fully coalesced against g_xh.  Final residual in K4 uses exact fp32 x.
// ---------------------------------------------------------------------------

#define BB   4
#define CC   512
#define NPOS (64*33)
#define NBQ  8
#define LAMBDA 0.01f
#define TWO_PI 6.28318530717958647692f

// Scratch.  Z/D channel-major packed: g_Z[(b*512+ch)*2112 + pos] = (zr, zi)
__device__ __half2 g_Z[(size_t)BB*CC*NPOS];
__device__ __half2 g_D[(size_t)BB*CC*NPOS];
__device__ __half g_u[(size_t)BB*CC*128*128];          // u fp16 [b][c][s]
__device__ __half g_xh[(size_t)BB*CC*128*128];         // x fp16 [b][c][s]
__device__ __half g_fw[(size_t)CC*CC];                 // fw fp16 [o][c]
// fixed matrices, PRE-SWIZZLED, single fp16 (compact packing, cols/rows 0..65)
__device__ __align__(16) __half g_TW[4][16384];
__device__ __align__(16) __half g_W1[NBQ][16384];      // [[wr,wi],[-wi,wr]]
__device__ __align__(16) __half g_W2[NBQ][16384];
__device__ float g_Bp[NBQ][256];

// ======================= helpers =============================
__device__ __forceinline__ uint32_t smem_u32(const void* p) {
    uint32_t a;
    asm("{ .reg .u64 t; cvta.to.shared.u64 t, %1; cvt.u32.u64 %0, t; }"
        : "=r"(a) : "l"(p));
    return a;
}
#define CP16(dst, src) \
    asm volatile("cp.async.cg.shared.global [%0], [%1], 16;" \
        :: "r"(dst), "l"(src) : "memory")
#define CP_COMMIT() asm volatile("cp.async.commit_group;" ::: "memory")
#define CP_WAIT(n)  asm volatile("cp.async.wait_group %0;" :: "n"(n) : "memory")

#define LDSM4(R, a) \
    asm volatile("ldmatrix.sync.aligned.m8n8.x4.shared.b16 {%0,%1,%2,%3}, [%4];" \
        : "=r"((R)[0]), "=r"((R)[1]), "=r"((R)[2]), "=r"((R)[3]) : "r"(a))
#define LDSM4T(R, a) \
    asm volatile("ldmatrix.sync.aligned.m8n8.x4.trans.shared.b16 {%0,%1,%2,%3}, [%4];" \
        : "=r"((R)[0]), "=r"((R)[1]), "=r"((R)[2]), "=r"((R)[3]) : "r"(a))
#define MMA_F16(C, A, B0, B1) \
    asm volatile("mma.sync.aligned.m16n8k16.row.col.f32.f16.f16.f32 " \
        "{%0,%1,%2,%3},{%4,%5,%6,%7},{%8,%9},{%0,%1,%2,%3};" \
        : "+f"((C)[0]), "+f"((C)[1]), "+f"((C)[2]), "+f"((C)[3]) \
        : "r"((A)[0]), "r"((A)[1]), "r"((A)[2]), "r"((A)[3]), "r"(B0), "r"(B1))

__device__ __forceinline__ uint32_t hp2(float a, float b) {
    __half2 h = __floats2half2_rn(a, b);
    return *(uint32_t*)&h;
}

// smem: data single 32K @0, fixed single 32K @32768; fp32 staging buffer
// (128x129 floats) overlays both; half staging stride-136 also overlays;
// bias at 66560 (1KB).
#define RD_O 0
#define RT_O 32768
#define BIAS_OFF 66560
#define SMEM_K 67584

__device__ __forceinline__ uint32_t sw_addr(int r, int c) {
    return (uint32_t)(r*256 + ((((c>>3) ^ (r&7)))<<4) + ((c&7)<<1));
}
__device__ __forceinline__ void wr2(char* smc, int r, int c, float v0, float v1) {
    *(uint32_t*)(smc + RD_O + sw_addr(r, c)) = hp2(v0, v1);
}
__device__ __forceinline__ void wr1(char* smc, int r, int c, float v) {
    *(__half*)(smc + RD_O + sw_addr(r, c)) = __float2half_rn(v);
}

// C += A @ B: A = data (RD), B = fixed (RT). kcN K-chunks of 16.
__device__ __forceinline__ void gemm_ssA(
    uint32_t sb, float c[2][4][4], int lane, int wm, int wn, int kcN)
{
    const int lrow8 = (lane & 7) + 8*((lane >> 3) & 1);
    const int lsel  = lane >> 4;
    #pragma unroll
    for (int kc = 0; kc < kcN; ++kc) {
        uint32_t ah[2][4], bh[2][4];
        #pragma unroll
        for (int mt = 0; mt < 2; ++mt) {
            int row  = wm*32 + mt*16 + lrow8;
            int unit = kc*2 + lsel;
            uint32_t off = (uint32_t)(row*256 + ((unit ^ (row&7))<<4));
            LDSM4(ah[mt], sb + RD_O + off);
        }
        #pragma unroll
        for (int nq = 0; nq < 2; ++nq) {
            int krow = kc*16 + lrow8;
            int unit = wn*4 + nq*2 + lsel;
            uint32_t off = (uint32_t)(krow*256 + ((unit ^ (krow&7))<<4));
            LDSM4T(bh[nq], sb + RT_O + off);
        }
        #pragma unroll
        for (int mt = 0; mt < 2; ++mt)
            #pragma unroll
            for (int nt = 0; nt < 4; ++nt) {
                int nq = nt >> 1, hb = (nt & 1)*2;
                MMA_F16(c[mt][nt], ah[mt], bh[nq][hb], bh[nq][hb+1]);
            }
    }
}

// C += A @ B: A = fixed (RT), B = data (RD).
__device__ __forceinline__ void gemm_ssB(
    uint32_t sb, float c[2][4][4], int lane, int wm, int wn, int kcN)
{
    const int lrow8 = (lane & 7) + 8*((lane >> 3) & 1);
    const int lsel  = lane >> 4;
    #pragma unroll
    for (int kc = 0; kc < kcN; ++kc) {
        uint32_t ah[2][4], bh[2][4];
        #pragma unroll
        for (int mt = 0; mt < 2; ++mt) {
            int row  = wm*32 + mt*16 + lrow8;
            int unit = kc*2 + lsel;
            uint32_t off = (uint32_t)(row*256 + ((unit ^ (row&7))<<4));
            LDSM4(ah[mt], sb + RT_O + off);
        }
        #pragma unroll
        for (int nq = 0; nq < 2; ++nq) {
            int krow = kc*16 + lrow8;
            int unit = wn*4 + nq*2 + lsel;
            uint32_t off = (uint32_t)(krow*256 + ((unit ^ (krow&7))<<4));
            LDSM4T(bh[nq], sb + RD_O + off);
        }
        #pragma unroll
        for (int mt = 0; mt < 2; ++mt)
            #pragma unroll
            for (int nt = 0; nt < 4; ++nt) {
                int nq = nt >> 1, hb = (nt & 1)*2;
                MMA_F16(c[mt][nt], ah[mt], bh[nq][hb], bh[nq][hb+1]);
            }
    }
}

#define ZERO_C(c) do { \
    _Pragma("unroll") for (int i_ = 0; i_ < 2; ++i_) \
        _Pragma("unroll") for (int j_ = 0; j_ < 4; ++j_) { \
            (c)[i_][j_][0]=0.f; (c)[i_][j_][1]=0.f; \
            (c)[i_][j_][2]=0.f; (c)[i_][j_][3]=0.f; } \
} while (0)

// async copy of one 32KB fixed matrix into RT
__device__ __forceinline__ void cpT(uint32_t sb, const __half* src, int t) {
    const char* s = (const char*)src;
    for (int i = t; i < 2048; i += 512)
        CP16(sb + RT_O + i*16, s + i*16);
    CP_COMMIT();
}

// ---------------------------------------------------------------------------
// k_prep: fused prologue — twiddles + MLP weight pack + biases + fw convert
// ---------------------------------------------------------------------------
__global__ __launch_bounds__(256) void k_prep(
    const float* __restrict__ w1r, const float* __restrict__ w1i,
    const float* __restrict__ w2r, const float* __restrict__ w2i,
    const float* __restrict__ b1r, const float* __restrict__ b1i,
    const float* __restrict__ b2r, const float* __restrict__ b2i,
    const float* __restrict__ fw)
{
    int idx = blockIdx.x*256 + threadIdx.x;      // 0..262143

    if (idx < 65536) {
        int mat = idx >> 14;
        int r   = (idx >> 7) & 127;
        int cq  = idx & 127;
        float v = 0.0f;
        const float W = TWO_PI / 128.0f;
        if (mat == 0) {
            if (cq < 33)       v =  cosf(W*((r*cq) & 127));
            else if (cq < 66)  v = -sinf(W*((r*(cq-33)) & 127));
        } else if (mat == 1) {
            if (r < 64) v = cosf(W*((r*cq) & 127));
            else        v = sinf(W*(((r-64)*cq) & 127));
        } else if (mat == 2) {
            if (cq < 64) v =  cosf(W*((r*cq) & 127));
            else         v = -sinf(W*(((cq-64)*r) & 127));
        } else {
            if (r < 33)       v =  cosf(W*((r*cq) & 127));
            else if (r < 66)  v = -sinf(W*(((r-33)*cq) & 127));
        }
        g_TW[mat][sw_addr(r, cq) >> 1] = __float2half_rn(v);
    }

    {
        int l   = idx >> 17;
        int rem = idx & 131071;
        int n   = rem >> 14;
        int r   = (rem >> 7) & 127;
        int cq  = rem & 127;
        const float* wr;
        const float* wi;
        if (l == 0) { wr = w1r; wi = w1i; } else { wr = w2r; wi = w2i; }
        float v;
        if (r < 64) v = (cq < 64) ?  wr[n*4096 + r*64 + cq]
                                  :  wi[n*4096 + r*64 + (cq-64)];
        else        v = (cq < 64) ? -wi[n*4096 + (r-64)*64 + cq]
                                  :  wr[n*4096 + (r-64)*64 + (cq-64)];
        uint32_t ei = sw_addr(r, cq) >> 1;
        if (l == 0) g_W1[n][ei] = __float2half_rn(v);
        else        g_W2[n][ei] = __float2half_rn(v);
    }

    if (idx < NBQ*256) {
        int bn = idx >> 8, j = idx & 255;
        float bv;
        if      (j < 64)  bv = b1r[bn*64 + j];
        else if (j < 128) bv = b1i[bn*64 + j - 64];
        else if (j < 192) bv = b2r[bn*64 + j - 128];
        else              bv = b2i[bn*64 + j - 192];
        g_Bp[bn][j] = bv;
    }

    g_fw[idx] = __float2half_rn(fw[idx]);
}

// ---------------------------------------------------------------------------
// K1: forward restricted rfft2.  Also emits g_xh = fp16(x) (coalesced).
// Cols 66..127 of both stage outputs exactly zero => wn==3 warps skip GEMMs.
// ---------------------------------------------------------------------------
__global__ __launch_bounds__(512, 2) void k_fwd_mma(const float* __restrict__ x)
{
    extern __shared__ char smc[];
    const uint32_t sb = smem_u32(smc);
    const int t = threadIdx.x, lane = t & 31, wid = t >> 5;
    const int wm = wid >> 2, wn = wid & 3;
    const int g = lane >> 2, tq = lane & 3;
    const int img = blockIdx.x, bimg = img >> 9, ch = img & 511;
    const float* src = x + (size_t)img * 16384;
    __half* xh = g_xh + (size_t)img * 16384;

    cpT(sb, g_TW[0], t);                          // B1 -> RT (async)
    for (int i = t*4; i < 16384; i += 2048) {
        float4 v = *(const float4*)(src + i);
        int r = i >> 7, c0 = i & 127;
        uint32_t off = sw_addr(r, c0);
        uint2 hh = { hp2(v.x, v.y), hp2(v.z, v.w) };
        *(uint2*)(smc + RD_O + off) = hh;
        *(uint2*)(xh + i) = hh;                   // fp16 x, coalesced
    }
    CP_WAIT(0);
    __syncthreads();

    float c[2][4][4];
    ZERO_C(c);
    if (wn != 3) gemm_ssA(sb, c, lane, wm, wn, 8);   // mid = X @ B1
    __syncthreads();

    #pragma unroll
    for (int mt = 0; mt < 2; ++mt)
        #pragma unroll
        for (int nt = 0; nt < 4; ++nt) {
            int r0 = wm*32 + mt*16 + g, cb = wn*32 + nt*8 + tq*2;
            wr2(smc, r0,     cb, c[mt][nt][0], c[mt][nt][1]);
            wr2(smc, r0 + 8, cb, c[mt][nt][2], c[mt][nt][3]);
        }
    cpT(sb, g_TW[1], t);                          // B2^T -> RT (async)
    CP_WAIT(0);
    __syncthreads();

    ZERO_C(c);
    if (wn != 3) gemm_ssB(sb, c, lane, wm, wn, 8);   // outT = B2^T @ mid
    __syncthreads();

    float* fbuf = (float*)smc;                        // [128][129]
    #pragma unroll
    for (int mt = 0; mt < 2; ++mt)
        #pragma unroll
        for (int nt = 0; nt < 4; ++nt) {
            int r0 = wm*32 + mt*16 + g, cb = wn*32 + nt*8 + tq*2;
            fbuf[r0*129 + cb]       = c[mt][nt][0];
            fbuf[r0*129 + cb + 1]   = c[mt][nt][1];
            fbuf[(r0+8)*129 + cb]   = c[mt][nt][2];
            fbuf[(r0+8)*129 + cb+1] = c[mt][nt][3];
        }
    __syncthreads();

    const size_t base = ((size_t)bimg*512 + ch) * NPOS;
    for (int o = t; o < NPOS; o += 512) {
        int k = o / 33, m = o - k*33;
        float zr = (fbuf[k*129 + m]      + fbuf[(64+k)*129 + 33+m]) * 0.0078125f;
        float zi = (fbuf[k*129 + 33+m]   - fbuf[(64+k)*129 + m])    * 0.0078125f;
        g_Z[base + o] = __floats2half2_rn(zr, zi);
    }
}

// ---------------------------------------------------------------------------
// K2: block-diagonal complex MLP.  Z/D packed half2.
// ---------------------------------------------------------------------------
__global__ __launch_bounds__(512, 2) void k_mlp_mma(void)
{
    extern __shared__ char smc[];
    const uint32_t sb = smem_u32(smc);
    const int t = threadIdx.x, lane = t & 31, wid = t >> 5;
    const int wm = wid >> 2, wn = wid & 3;
    const int g = lane >> 2, tq = lane & 3;
    const int n  = blockIdx.y;
    const int p0 = blockIdx.x * 128;
    float* bias = (float*)(smc + BIAS_OFF);

    const int posl = t & 127;
    const int gq   = t >> 7;          // 0..3, each handles 16 channels
    const int Pg   = p0 + posl;
    const int bg   = Pg / NPOS, posg = Pg - bg*NPOS;

    cpT(sb, g_W1[n], t);                          // W1 -> RT (async)
    {   // load z packed -> RD [pos][ zr cols 0..63 | zi cols 64..127 ]
        const __half2* zb = g_Z + ((size_t)bg*512 + n*64 + gq*16)*NPOS + posg;
        #pragma unroll
        for (int it = 0; it < 8; ++it) {
            __half2 a  = zb[(size_t)(2*it)*NPOS];
            __half2 bq = zb[(size_t)(2*it+1)*NPOS];
            __half2 lo = __lows2half2(a, bq);
            __half2 hi = __highs2half2(a, bq);
            int cc = gq*16 + 2*it;
            *(uint32_t*)(smc + RD_O + sw_addr(posl, cc))      = *(uint32_t*)&lo;
            *(uint32_t*)(smc + RD_O + sw_addr(posl, 64 + cc)) = *(uint32_t*)&hi;
        }
    }
    if (t < 256) bias[t] = g_Bp[n][t];
    CP_WAIT(0);
    __syncthreads();

    float c[2][4][4];
    ZERO_C(c);
    gemm_ssA(sb, c, lane, wm, wn, 8);               // y1 = z @ W1
    __syncthreads();

    #pragma unroll
    for (int mt = 0; mt < 2; ++mt)
        #pragma unroll
        for (int nt = 0; nt < 4; ++nt) {
            int r0 = wm*32 + mt*16 + g, cb = wn*32 + nt*8 + tq*2;
            float b0 = bias[cb], b1v = bias[cb+1];
            #pragma unroll
            for (int hrow = 0; hrow < 2; ++hrow) {
                float v0 = c[mt][nt][hrow*2+0] + b0;
                float v1 = c[mt][nt][hrow*2+1] + b1v;
                v0 = 0.5f * v0 * (1.0f + erff(v0 * 0.70710678118654752f));
                v1 = 0.5f * v1 * (1.0f + erff(v1 * 0.70710678118654752f));
                wr2(smc, r0 + hrow*8, cb, v0, v1);
            }
        }
    cpT(sb, g_W2[n], t);                          // W2 -> RT (async)
    CP_WAIT(0);
    __syncthreads();

    float cc2[2][4][4];
    ZERO_C(cc2);
    gemm_ssA(sb, cc2, lane, wm, wn, 8);             // y2 = h @ W2
    __syncthreads();

    float* fbuf = (float*)smc;
    #pragma unroll
    for (int mt = 0; mt < 2; ++mt)
        #pragma unroll
        for (int nt = 0; nt < 4; ++nt) {
            int r0 = wm*32 + mt*16 + g, cb = wn*32 + nt*8 + tq*2;
            float b0 = bias[128 + cb], b1v = bias[128 + cb + 1];
            #pragma unroll
            for (int hrow = 0; hrow < 2; ++hrow) {
                float v0 = cc2[mt][nt][hrow*2+0] + b0;
                float v1 = cc2[mt][nt][hrow*2+1] + b1v;
                float s0 = fabsf(v0) - LAMBDA; v0 = (s0 > 0.f) ? copysignf(s0, v0) : 0.f;
                float s1 = fabsf(v1) - LAMBDA; v1 = (s1 > 0.f) ? copysignf(s1, v1) : 0.f;
                fbuf[(r0 + hrow*8)*129 + cb]     = v0;
                fbuf[(r0 + hrow*8)*129 + cb + 1] = v1;
            }
        }
    __syncthreads();

    {   // D = y - z (packed), coalesced along pos
        const size_t zoff = ((size_t)bg*512 + n*64 + gq*16)*NPOS + posg;
        #pragma unroll
        for (int it = 0; it < 16; ++it) {
            int cc = gq*16 + it;
            float yr = fbuf[posl*129 + cc];
            float yi = fbuf[posl*129 + 64 + cc];
            float2 zf = __half22float2(g_Z[zoff + (size_t)it*NPOS]);
            g_D[zoff + (size_t)it*NPOS] = __floats2half2_rn(yr - zf.x, yi - zf.y);
        }
    }
}

// ---------------------------------------------------------------------------
// K3: u = xh + irfft2_ortho(D) -> single fp16 u.  Staged, coalesced epilogue.
// Compact dpack (rows/cols 0..65) => stage1 wn==3 skip; stage2 K-chunks 0..4.
// ---------------------------------------------------------------------------
__global__ __launch_bounds__(512, 2) void k_inv_mma(void)
{
    extern __shared__ char smc[];
    const uint32_t sb = smem_u32(smc);
    const int t = threadIdx.x, lane = t & 31, wid = t >> 5;
    const int wm = wid >> 2, wn = wid & 3;
    const int g = lane >> 2, tq = lane & 3;
    const int img = blockIdx.x, bimg = img >> 9, ch = img & 511;

    cpT(sb, g_TW[2], t);                          // B3^T -> RT (async)
    {   // zero RD (32KB)
        uint4 z = {0,0,0,0};
        uint4* pd = (uint4*)(smc + RD_O);
        for (int i = t; i < 2048; i += 512) pd[i] = z;
    }
    __syncthreads();

    // gather D -> dpack^T in RD: rows kk = k|64+k, cols = m | 33+m
    const size_t base = ((size_t)bimg*512 + ch) * NPOS;
    for (int o = t; o < NPOS; o += 512) {
        int k = o / 33, m = o - k*33;
        float2 df = __half22float2(g_D[base + o]);
        float a = df.x, b = df.y;
        if (m == 0) { a *= 0.5f; b *= 0.5f; }
        wr1(smc, k,      m,      a);
        wr1(smc, k,      33 + m, b);
        wr1(smc, 64 + k, m,      b);
        wr1(smc, 64 + k, 33 + m, -a);
    }
    CP_WAIT(0);
    __syncthreads();

    float c[2][4][4];
    ZERO_C(c);
    if (wn != 3) gemm_ssB(sb, c, lane, wm, wn, 8);   // G^T = B3^T @ dpack^T
    __syncthreads();

    #pragma unroll
    for (int mt = 0; mt < 2; ++mt)
        #pragma unroll
        for (int nt = 0; nt < 4; ++nt) {
            int r0 = wm*32 + mt*16 + g, cb = wn*32 + nt*8 + tq*2;
            wr2(smc, r0,     cb, c[mt][nt][0], c[mt][nt][1]);
            wr2(smc, r0 + 8, cb, c[mt][nt][2], c[mt][nt][3]);
        }
    cpT(sb, g_TW[3], t);                          // B4 -> RT (async)
    CP_WAIT(0);
    __syncthreads();

    ZERO_C(c);
    gemm_ssA(sb, c, lane, wm, wn, 5);                // v = G^T @ B4 (K<=80)
    __syncthreads();

    // stage scaled v into half buffer, stride 136 halves (bank-conflict-free)
    __half* stg = (__half*)smc;
    #pragma unroll
    for (int mt = 0; mt < 2; ++mt)
        #pragma unroll
        for (int nt = 0; nt < 4; ++nt) {
            int r0 = wm*32 + mt*16 + g, cb = wn*32 + nt*8 + tq*2;
            #pragma unroll
            for (int hrow = 0; hrow < 2; ++hrow) {
                int r = r0 + hrow*8;
                float v0 = c[mt][nt][hrow*2 + 0] * 0.015625f;
                float v1 = c[mt][nt][hrow*2 + 1] * 0.015625f;
                *(uint32_t*)(stg + r*136 + cb) = hp2(v0, v1);
            }
        }
    __syncthreads();

    // coalesced flush: u = xh + v
    const __half2* xh2 = (const __half2*)(g_xh + (size_t)img * 16384);
    __half2* up2 = (__half2*)(g_u + (size_t)img * 16384);
    #pragma unroll
    for (int it = 0; it < 16; ++it) {
        int i = t + it*512;                // u32 index 0..8191
        int r = i >> 6, cp = (i & 63) * 2;
        __half2 vv = *(__half2*)(stg + r*136 + cp);
        float2 vf = __half22float2(vv);
        float2 xf = __half22float2(xh2[i]);
        up2[i] = __floats2half2_rn(vf.x + xf.x, vf.y + xf.y);
    }
}

// ---------------------------------------------------------------------------
// K4: HMMA fp16 GEMM: A = fw single, B = u single.  out = x + fw @ u.
// CTA 128x128, 8 warps, K-chunk 32, cp.async 3 stages.
// ---------------------------------------------------------------------------
#define STG_B 16384
#define OFF_A 0
#define OFF_B 8192

__global__ __launch_bounds__(256, 2) void k_gemm_mma(
    const float* __restrict__ x, float* __restrict__ out)
{
    extern __shared__ char smc[];
    const uint32_t sb = smem_u32(smc);
    const int t    = threadIdx.x;
    const int lane = t & 31;
    const int wid  = t >> 5;
    const int wm   = wid >> 1;
    const int wn   = wid & 1;
    const int m0   = blockIdx.x * 128;
    const int n0g  = blockIdx.y * 128;
    const int bimg = n0g >> 14;
    const int s0   = n0g & 16383;

    const char* pA = (const char*)g_fw;
    const char* pB = (const char*)g_u;

    int ar0 = (t + 0)   >> 2, au0 = (t + 0)   & 3;
    int ar1 = (t + 256) >> 2, au1 = (t + 256) & 3;
    uint32_t adst0 = (uint32_t)(ar0*64 + ((au0 ^ ((ar0>>1)&3)) << 4));
    uint32_t adst1 = (uint32_t)(ar1*64 + ((au1 ^ ((ar1>>1)&3)) << 4));
    int br0 = (t + 0)   >> 4, bu0 = (t + 0)   & 15;
    int br1 = (t + 256) >> 4, bu1 = (t + 256) & 15;
    uint32_t bdst0 = (uint32_t)(br0*256 + ((bu0 ^ (br0&7)) << 4));
    uint32_t bdst1 = (uint32_t)(br1*256 + ((bu1 ^ (br1&7)) << 4));

    float c[2][8][4];
    #pragma unroll
    for (int i = 0; i < 2; ++i)
        #pragma unroll
        for (int j = 0; j < 8; ++j) {
            c[i][j][0] = 0.f; c[i][j][1] = 0.f; c[i][j][2] = 0.f; c[i][j][3] = 0.f;
        }

    const int lrow8 = (lane & 7) + 8*((lane >> 3) & 1);
    const int lsel  = lane >> 4;

    #define ISSUE_STAGE(kc, buf) do { \
        uint32_t st_ = sb + (buf)*STG_B; \
        { size_t so = ((size_t)(m0 + ar0)*512 + (kc)*32 + au0*8)*2; \
          CP16(st_ + OFF_A + adst0, pA + so); } \
        { size_t so = ((size_t)(m0 + ar1)*512 + (kc)*32 + au1*8)*2; \
          CP16(st_ + OFF_A + adst1, pA + so); } \
        { size_t so = ((size_t)(bimg*512 + (kc)*32 + br0)*16384 + s0 + bu0*8)*2; \
          CP16(st_ + OFF_B + bdst0, pB + so); } \
        { size_t so = ((size_t)(bimg*512 + (kc)*32 + br1)*16384 + s0 + bu1*8)*2; \
          CP16(st_ + OFF_B + bdst1, pB + so); } \
        CP_COMMIT(); \
    } while (0)

    ISSUE_STAGE(0, 0);
    ISSUE_STAGE(1, 1);
    ISSUE_STAGE(2, 2);

    for (int kc = 0; kc < 16; ++kc) {
        const int buf = kc % 3;
        if (kc < 14)      { CP_WAIT(2); }
        else if (kc == 14){ CP_WAIT(1); }
        else              { CP_WAIT(0); }
        __syncthreads();

        const uint32_t st = sb + buf*STG_B;
        #pragma unroll
        for (int ks = 0; ks < 2; ++ks) {
            uint32_t ah[2][4], bh[4][4];
            #pragma unroll
            for (int mt = 0; mt < 2; ++mt) {
                int row  = wm*32 + mt*16 + lrow8;
                int unit = ks*2 + lsel;
                uint32_t off = (uint32_t)(row*64 + ((unit ^ ((row>>1)&3)) << 4));
                LDSM4(ah[mt], st + OFF_A + off);
            }
            #pragma unroll
            for (int nq = 0; nq < 4; ++nq) {
                int krow = ks*16 + lrow8;
                int unit = wn*8 + nq*2 + lsel;
                uint32_t off = (uint32_t)(krow*256 + ((unit ^ (krow&7)) << 4));
                LDSM4T(bh[nq], st + OFF_B + off);
            }
            #pragma unroll
            for (int mt = 0; mt < 2; ++mt)
                #pragma unroll
                for (int nt = 0; nt < 8; ++nt) {
                    const int nq = nt >> 1, hb = (nt & 1) * 2;
                    MMA_F16(c[mt][nt], ah[mt], bh[nq][hb], bh[nq][hb+1]);
                }
        }
        __syncthreads();
        if (kc + 3 < 16) ISSUE_STAGE(kc + 3, (kc + 3) % 3);
    }

    const int g  = lane >> 2;
    const int tq = lane & 3;
    const size_t obase = (size_t)(bimg * 512);
    #pragma unroll
    for (int mt = 0; mt < 2; ++mt)
        #pragma unroll
        for (int nt = 0; nt < 8; ++nt) {
            int row0 = m0 + wm*32 + mt*16 + g;
            int col  = s0 + wn*64 + nt*8 + tq*2;
            size_t go = (obase + row0)*16384 + col;
            float2 xv = *(const float2*)(x + go);
            float2 ov = { c[mt][nt][0] + xv.x, c[mt][nt][1] + xv.y };
            *(float2*)(out + go) = ov;
            go += (size_t)8 * 16384;
            xv = *(const float2*)(x + go);
            float2 ov2 = { c[mt][nt][2] + xv.x, c[mt][nt][3] + xv.y };
            *(float2*)(out + go) = ov2;
        }
}

// ---------------------------------------------------------------------------
#define SMEM_GMM (3 * STG_B)

extern "C" void kernel_launch(void* const* d_in, const int* in_sizes, int n_in,
                              void* d_out, int out_size)
{
    const float* x   = (const float*)d_in[0];
    const float* w1r = (const float*)d_in[1];
    const float* w1i = (const float*)d_in[2];
    const float* b1r = (const float*)d_in[3];
    const float* b1i = (const float*)d_in[4];
    const float* w2r = (const float*)d_in[5];
    const float* w2i = (const float*)d_in[6];
    const float* b2r = (const float*)d_in[7];
    const float* b2i = (const float*)d_in[8];
    const float* fw  = (const float*)d_in[9];
    float* out = (float*)d_out;

    cudaFuncSetAttribute(k_fwd_mma, cudaFuncAttributeMaxDynamicSharedMemorySize, SMEM_K);
    cudaFuncSetAttribute(k_inv_mma, cudaFuncAttributeMaxDynamicSharedMemorySize, SMEM_K);
    cudaFuncSetAttribute(k_mlp_mma, cudaFuncAttributeMaxDynamicSharedMemorySize, SMEM_K);
    cudaFuncSetAttribute(k_gemm_mma,cudaFuncAttributeMaxDynamicSharedMemorySize, SMEM_GMM);

    k_prep<<<1024, 256>>>(w1r, w1i, w2r, w2i, b1r, b1i, b2r, b2i, fw);

    k_fwd_mma<<<BB*CC, 512, SMEM_K>>>(x);

    dim3 g2((BB*NPOS)/128, NBQ);
    k_mlp_mma<<<g2, 512, SMEM_K>>>();

    k_inv_mma<<<BB*CC, 512, SMEM_K>>>();

    dim3 gg(4, BB*16384/128);
    k_gemm_mma<<<gg, 256, SMEM_GMM>>>(x, out);
}

// round 16
// speedup vs baseline: 1.0890x; 1.0890x over previous
#include <cuda_runtime.h>
#include <cuda_fp16.h>
#include <math.h>
#include <stdint.h>

// ---------------------------------------------------------------------------
// AFNO2D: out = x + fuse_w @ (x + irfft2(D)),   D = masked_MLP(Z) - Z on the
// 64x33 low-frequency region of Z = rfft2(x, ortho).
// HMMA fp16 single-precision in the frequency path.  Z/D packed half2,
// channel-major.  Round 16: BOTH fixed matrices preloaded at kernel start
// (RT0+RT1 resident, 99KB smem, still 2 CTAs/SM) — removes the mid-kernel
// cp.async wait + one barrier phase from every DFT/MLP kernel.
// ---------------------------------------------------------------------------

#define BB   4
#define CC   512
#define NPOS (64*33)
#define NBQ  8
#define LAMBDA 0.01f
#define TWO_PI 6.28318530717958647692f

// Scratch.  Z/D channel-major packed: g_Z[(b*512+ch)*2112 + pos] = (zr, zi)
__device__ __half2 g_Z[(size_t)BB*CC*NPOS];
__device__ __half2 g_D[(size_t)BB*CC*NPOS];
__device__ __half g_u[(size_t)BB*CC*128*128];          // u fp16 [b][c][s]
__device__ __half g_fw[(size_t)CC*CC];                 // fw fp16 [o][c]
// fixed matrices, PRE-SWIZZLED, single fp16 (compact packing, cols/rows 0..65)
__device__ __align__(16) __half g_TW[4][16384];
__device__ __align__(16) __half g_W1[NBQ][16384];      // [[wr,wi],[-wi,wr]]
__device__ __align__(16) __half g_W2[NBQ][16384];
__device__ float g_Bp[NBQ][256];

// ======================= helpers =============================
__device__ __forceinline__ uint32_t smem_u32(const void* p) {
    uint32_t a;
    asm("{ .reg .u64 t; cvta.to.shared.u64 t, %1; cvt.u32.u64 %0, t; }"
        : "=r"(a) : "l"(p));
    return a;
}
#define CP16(dst, src) \
    asm volatile("cp.async.cg.shared.global [%0], [%1], 16;" \
        :: "r"(dst), "l"(src) : "memory")
#define CP_COMMIT() asm volatile("cp.async.commit_group;" ::: "memory")
#define CP_WAIT(n)  asm volatile("cp.async.wait_group %0;" :: "n"(n) : "memory")

#define LDSM4(R, a) \
    asm volatile("ldmatrix.sync.aligned.m8n8.x4.shared.b16 {%0,%1,%2,%3}, [%4];" \
        : "=r"((R)[0]), "=r"((R)[1]), "=r"((R)[2]), "=r"((R)[3]) : "r"(a))
#define LDSM4T(R, a) \
    asm volatile("ldmatrix.sync.aligned.m8n8.x4.trans.shared.b16 {%0,%1,%2,%3}, [%4];" \
        : "=r"((R)[0]), "=r"((R)[1]), "=r"((R)[2]), "=r"((R)[3]) : "r"(a))
#define MMA_F16(C, A, B0, B1) \
    asm volatile("mma.sync.aligned.m16n8k16.row.col.f32.f16.f16.f32 " \
        "{%0,%1,%2,%3},{%4,%5,%6,%7},{%8,%9},{%0,%1,%2,%3};" \
        : "+f"((C)[0]), "+f"((C)[1]), "+f"((C)[2]), "+f"((C)[3]) \
        : "r"((A)[0]), "r"((A)[1]), "r"((A)[2]), "r"((A)[3]), "r"(B0), "r"(B1))

__device__ __forceinline__ uint32_t hp2(float a, float b) {
    __half2 h = __floats2half2_rn(a, b);
    return *(uint32_t*)&h;
}

// smem: data 32K @0, fixed0 32K @32768, fixed1 32K @65536, bias @98304.
// fp32 staging buffer (128x129 floats = 66048B) overlays RD+RT0.
#define RD_O  0
#define RT0_O 32768
#define RT1_O 65536
#define BIAS_OFF 98304
#define SMEM_K 99328

__device__ __forceinline__ uint32_t sw_addr(int r, int c) {
    return (uint32_t)(r*256 + ((((c>>3) ^ (r&7)))<<4) + ((c&7)<<1));
}
__device__ __forceinline__ void wr2(char* smc, int r, int c, float v0, float v1) {
    *(uint32_t*)(smc + RD_O + sw_addr(r, c)) = hp2(v0, v1);
}
__device__ __forceinline__ void wr1(char* smc, int r, int c, float v) {
    *(__half*)(smc + RD_O + sw_addr(r, c)) = __float2half_rn(v);
}

// C += A @ B: A = data (RD), B = fixed (rt). kcN K-chunks of 16.
__device__ __forceinline__ void gemm_ssA(
    uint32_t sb, float c[2][4][4], int lane, int wm, int wn, int kcN, uint32_t rt)
{
    const int lrow8 = (lane & 7) + 8*((lane >> 3) & 1);
    const int lsel  = lane >> 4;
    #pragma unroll
    for (int kc = 0; kc < kcN; ++kc) {
        uint32_t ah[2][4], bh[2][4];
        #pragma unroll
        for (int mt = 0; mt < 2; ++mt) {
            int row  = wm*32 + mt*16 + lrow8;
            int unit = kc*2 + lsel;
            uint32_t off = (uint32_t)(row*256 + ((unit ^ (row&7))<<4));
            LDSM4(ah[mt], sb + RD_O + off);
        }
        #pragma unroll
        for (int nq = 0; nq < 2; ++nq) {
            int krow = kc*16 + lrow8;
            int unit = wn*4 + nq*2 + lsel;
            uint32_t off = (uint32_t)(krow*256 + ((unit ^ (krow&7))<<4));
            LDSM4T(bh[nq], sb + rt + off);
        }
        #pragma unroll
        for (int mt = 0; mt < 2; ++mt)
            #pragma unroll
            for (int nt = 0; nt < 4; ++nt) {
                int nq = nt >> 1, hb = (nt & 1)*2;
                MMA_F16(c[mt][nt], ah[mt], bh[nq][hb], bh[nq][hb+1]);
            }
    }
}

// C += A @ B: A = fixed (rt), B = data (RD).
__device__ __forceinline__ void gemm_ssB(
    uint32_t sb, float c[2][4][4], int lane, int wm, int wn, int kcN, uint32_t rt)
{
    const int lrow8 = (lane & 7) + 8*((lane >> 3) & 1);
    const int lsel  = lane >> 4;
    #pragma unroll
    for (int kc = 0; kc < kcN; ++kc) {
        uint32_t ah[2][4], bh[2][4];
        #pragma unroll
        for (int mt = 0; mt < 2; ++mt) {
            int row  = wm*32 + mt*16 + lrow8;
            int unit = kc*2 + lsel;
            uint32_t off = (uint32_t)(row*256 + ((unit ^ (row&7))<<4));
            LDSM4(ah[mt], sb + rt + off);
        }
        #pragma unroll
        for (int nq = 0; nq < 2; ++nq) {
            int krow = kc*16 + lrow8;
            int unit = wn*4 + nq*2 + lsel;
            uint32_t off = (uint32_t)(krow*256 + ((unit ^ (krow&7))<<4));
            LDSM4T(bh[nq], sb + RD_O + off);
        }
        #pragma unroll
        for (int mt = 0; mt < 2; ++mt)
            #pragma unroll
            for (int nt = 0; nt < 4; ++nt) {
                int nq = nt >> 1, hb = (nt & 1)*2;
                MMA_F16(c[mt][nt], ah[mt], bh[nq][hb], bh[nq][hb+1]);
            }
    }
}

#define ZERO_C(c) do { \
    _Pragma("unroll") for (int i_ = 0; i_ < 2; ++i_) \
        _Pragma("unroll") for (int j_ = 0; j_ < 4; ++j_) { \
            (c)[i_][j_][0]=0.f; (c)[i_][j_][1]=0.f; \
            (c)[i_][j_][2]=0.f; (c)[i_][j_][3]=0.f; } \
} while (0)

// async copy of one 32KB fixed matrix into region rt
__device__ __forceinline__ void cpT(uint32_t sb, uint32_t rt, const __half* src, int t) {
    const char* s = (const char*)src;
    for (int i = t; i < 2048; i += 512)
        CP16(sb + rt + i*16, s + i*16);
    CP_COMMIT();
}

// ---------------------------------------------------------------------------
// k_prep: fused prologue — twiddles + MLP weight pack + biases + fw convert
// ---------------------------------------------------------------------------
__global__ __launch_bounds__(256) void k_prep(
    const float* __restrict__ w1r, const float* __restrict__ w1i,
    const float* __restrict__ w2r, const float* __restrict__ w2i,
    const float* __restrict__ b1r, const float* __restrict__ b1i,
    const float* __restrict__ b2r, const float* __restrict__ b2i,
    const float* __restrict__ fw)
{
    int idx = blockIdx.x*256 + threadIdx.x;      // 0..262143

    if (idx < 65536) {
        int mat = idx >> 14;
        int r   = (idx >> 7) & 127;
        int cq  = idx & 127;
        float v = 0.0f;
        const float W = TWO_PI / 128.0f;
        if (mat == 0) {
            if (cq < 33)       v =  cosf(W*((r*cq) & 127));
            else if (cq < 66)  v = -sinf(W*((r*(cq-33)) & 127));
        } else if (mat == 1) {
            if (r < 64) v = cosf(W*((r*cq) & 127));
            else        v = sinf(W*(((r-64)*cq) & 127));
        } else if (mat == 2) {
            if (cq < 64) v =  cosf(W*((r*cq) & 127));
            else         v = -sinf(W*(((cq-64)*r) & 127));
        } else {
            if (r < 33)       v =  cosf(W*((r*cq) & 127));
            else if (r < 66)  v = -sinf(W*(((r-33)*cq) & 127));
        }
        g_TW[mat][sw_addr(r, cq) >> 1] = __float2half_rn(v);
    }

    {
        int l   = idx >> 17;
        int rem = idx & 131071;
        int n   = rem >> 14;
        int r   = (rem >> 7) & 127;
        int cq  = rem & 127;
        const float* wr;
        const float* wi;
        if (l == 0) { wr = w1r; wi = w1i; } else { wr = w2r; wi = w2i; }
        float v;
        if (r < 64) v = (cq < 64) ?  wr[n*4096 + r*64 + cq]
                                  :  wi[n*4096 + r*64 + (cq-64)];
        else        v = (cq < 64) ? -wi[n*4096 + (r-64)*64 + cq]
                                  :  wr[n*4096 + (r-64)*64 + (cq-64)];
        uint32_t ei = sw_addr(r, cq) >> 1;
        if (l == 0) g_W1[n][ei] = __float2half_rn(v);
        else        g_W2[n][ei] = __float2half_rn(v);
    }

    if (idx < NBQ*256) {
        int bn = idx >> 8, j = idx & 255;
        float bv;
        if      (j < 64)  bv = b1r[bn*64 + j];
        else if (j < 128) bv = b1i[bn*64 + j - 64];
        else if (j < 192) bv = b2r[bn*64 + j - 128];
        else              bv = b2i[bn*64 + j - 192];
        g_Bp[bn][j] = bv;
    }

    g_fw[idx] = __float2half_rn(fw[idx]);
}

// ---------------------------------------------------------------------------
// K1: forward restricted rfft2.  Both twiddles preloaded; one barrier fewer.
// Cols 66..127 of both stage outputs exactly zero => wn==3 warps skip GEMMs.
// ---------------------------------------------------------------------------
__global__ __launch_bounds__(512, 2) void k_fwd_mma(const float* __restrict__ x)
{
    extern __shared__ char smc[];
    const uint32_t sb = smem_u32(smc);
    const int t = threadIdx.x, lane = t & 31, wid = t >> 5;
    const int wm = wid >> 2, wn = wid & 3;
    const int g = lane >> 2, tq = lane & 3;
    const int img = blockIdx.x, bimg = img >> 9, ch = img & 511;
    const float* src = x + (size_t)img * 16384;

    cpT(sb, RT0_O, g_TW[0], t);                   // B1   -> RT0 (async)
    cpT(sb, RT1_O, g_TW[1], t);                   // B2^T -> RT1 (async)
    for (int i = t*4; i < 16384; i += 2048) {
        float4 v = *(const float4*)(src + i);
        int r = i >> 7, c0 = i & 127;
        uint32_t off = sw_addr(r, c0);
        uint2 hh = { hp2(v.x, v.y), hp2(v.z, v.w) };
        *(uint2*)(smc + RD_O + off) = hh;
    }
    CP_WAIT(0);
    __syncthreads();

    float c[2][4][4];
    ZERO_C(c);
    if (wn != 3) gemm_ssA(sb, c, lane, wm, wn, 8, RT0_O);   // mid = X @ B1
    __syncthreads();

    #pragma unroll
    for (int mt = 0; mt < 2; ++mt)
        #pragma unroll
        for (int nt = 0; nt < 4; ++nt) {
            int r0 = wm*32 + mt*16 + g, cb = wn*32 + nt*8 + tq*2;
            wr2(smc, r0,     cb, c[mt][nt][0], c[mt][nt][1]);
            wr2(smc, r0 + 8, cb, c[mt][nt][2], c[mt][nt][3]);
        }
    __syncthreads();

    ZERO_C(c);
    if (wn != 3) gemm_ssB(sb, c, lane, wm, wn, 8, RT1_O);   // outT = B2^T @ mid
    __syncthreads();

    float* fbuf = (float*)smc;                        // [128][129]
    #pragma unroll
    for (int mt = 0; mt < 2; ++mt)
        #pragma unroll
        for (int nt = 0; nt < 4; ++nt) {
            int r0 = wm*32 + mt*16 + g, cb = wn*32 + nt*8 + tq*2;
            fbuf[r0*129 + cb]       = c[mt][nt][0];
            fbuf[r0*129 + cb + 1]   = c[mt][nt][1];
            fbuf[(r0+8)*129 + cb]   = c[mt][nt][2];
            fbuf[(r0+8)*129 + cb+1] = c[mt][nt][3];
        }
    __syncthreads();

    const size_t base = ((size_t)bimg*512 + ch) * NPOS;
    for (int o = t; o < NPOS; o += 512) {
        int k = o / 33, m = o - k*33;
        float zr = (fbuf[k*129 + m]      + fbuf[(64+k)*129 + 33+m]) * 0.0078125f;
        float zi = (fbuf[k*129 + 33+m]   - fbuf[(64+k)*129 + m])    * 0.0078125f;
        g_Z[base + o] = __floats2half2_rn(zr, zi);
    }
}

// ---------------------------------------------------------------------------
// K2: block-diagonal complex MLP.  W1+W2 preloaded.
// ---------------------------------------------------------------------------
__global__ __launch_bounds__(512, 2) void k_mlp_mma(void)
{
    extern __shared__ char smc[];
    const uint32_t sb = smem_u32(smc);
    const int t = threadIdx.x, lane = t & 31, wid = t >> 5;
    const int wm = wid >> 2, wn = wid & 3;
    const int g = lane >> 2, tq = lane & 3;
    const int n  = blockIdx.y;
    const int p0 = blockIdx.x * 128;
    float* bias = (float*)(smc + BIAS_OFF);

    const int posl = t & 127;
    const int gq   = t >> 7;          // 0..3, each handles 16 channels
    const int Pg   = p0 + posl;
    const int bg   = Pg / NPOS, posg = Pg - bg*NPOS;

    cpT(sb, RT0_O, g_W1[n], t);                   // W1 -> RT0 (async)
    cpT(sb, RT1_O, g_W2[n], t);                   // W2 -> RT1 (async)
    {   // load z packed -> RD [pos][ zr cols 0..63 | zi cols 64..127 ]
        const __half2* zb = g_Z + ((size_t)bg*512 + n*64 + gq*16)*NPOS + posg;
        #pragma unroll
        for (int it = 0; it < 8; ++it) {
            __half2 a  = zb[(size_t)(2*it)*NPOS];
            __half2 bq = zb[(size_t)(2*it+1)*NPOS];
            __half2 lo = __lows2half2(a, bq);
            __half2 hi = __highs2half2(a, bq);
            int cc = gq*16 + 2*it;
            *(uint32_t*)(smc + RD_O + sw_addr(posl, cc))      = *(uint32_t*)&lo;
            *(uint32_t*)(smc + RD_O + sw_addr(posl, 64 + cc)) = *(uint32_t*)&hi;
        }
    }
    if (t < 256) bias[t] = g_Bp[n][t];
    CP_WAIT(0);
    __syncthreads();

    float c[2][4][4];
    ZERO_C(c);
    gemm_ssA(sb, c, lane, wm, wn, 8, RT0_O);        // y1 = z @ W1
    __syncthreads();

    #pragma unroll
    for (int mt = 0; mt < 2; ++mt)
        #pragma unroll
        for (int nt = 0; nt < 4; ++nt) {
            int r0 = wm*32 + mt*16 + g, cb = wn*32 + nt*8 + tq*2;
            float b0 = bias[cb], b1v = bias[cb+1];
            #pragma unroll
            for (int hrow = 0; hrow < 2; ++hrow) {
                float v0 = c[mt][nt][hrow*2+0] + b0;
                float v1 = c[mt][nt][hrow*2+1] + b1v;
                v0 = 0.5f * v0 * (1.0f + erff(v0 * 0.70710678118654752f));
                v1 = 0.5f * v1 * (1.0f + erff(v1 * 0.70710678118654752f));
                wr2(smc, r0 + hrow*8, cb, v0, v1);
            }
        }
    __syncthreads();

    float cc2[2][4][4];
    ZERO_C(cc2);
    gemm_ssA(sb, cc2, lane, wm, wn, 8, RT1_O);      // y2 = h @ W2
    __syncthreads();

    float* fbuf = (float*)smc;
    #pragma unroll
    for (int mt = 0; mt < 2; ++mt)
        #pragma unroll
        for (int nt = 0; nt < 4; ++nt) {
            int r0 = wm*32 + mt*16 + g, cb = wn*32 + nt*8 + tq*2;
            float b0 = bias[128 + cb], b1v = bias[128 + cb + 1];
            #pragma unroll
            for (int hrow = 0; hrow < 2; ++hrow) {
                float v0 = cc2[mt][nt][hrow*2+0] + b0;
                float v1 = cc2[mt][nt][hrow*2+1] + b1v;
                float s0 = fabsf(v0) - LAMBDA; v0 = (s0 > 0.f) ? copysignf(s0, v0) : 0.f;
                float s1 = fabsf(v1) - LAMBDA; v1 = (s1 > 0.f) ? copysignf(s1, v1) : 0.f;
                fbuf[(r0 + hrow*8)*129 + cb]     = v0;
                fbuf[(r0 + hrow*8)*129 + cb + 1] = v1;
            }
        }
    __syncthreads();

    {   // D = y - z (packed), coalesced along pos
        const size_t zoff = ((size_t)bg*512 + n*64 + gq*16)*NPOS + posg;
        #pragma unroll
        for (int it = 0; it < 16; ++it) {
            int cc = gq*16 + it;
            float yr = fbuf[posl*129 + cc];
            float yi = fbuf[posl*129 + 64 + cc];
            float2 zf = __half22float2(g_Z[zoff + (size_t)it*NPOS]);
            g_D[zoff + (size_t)it*NPOS] = __floats2half2_rn(yr - zf.x, yi - zf.y);
        }
    }
}

// ---------------------------------------------------------------------------
// K3: u = x + irfft2_ortho(D) -> single fp16 u.  Both twiddles preloaded.
// Compact dpack (rows/cols 0..65) => stage1 wn==3 skip; stage2 K-chunks 0..4.
// ---------------------------------------------------------------------------
__global__ __launch_bounds__(512, 2) void k_inv_mma(const float* __restrict__ x)
{
    extern __shared__ char smc[];
    const uint32_t sb = smem_u32(smc);
    const int t = threadIdx.x, lane = t & 31, wid = t >> 5;
    const int wm = wid >> 2, wn = wid & 3;
    const int g = lane >> 2, tq = lane & 3;
    const int img = blockIdx.x, bimg = img >> 9, ch = img & 511;

    cpT(sb, RT0_O, g_TW[2], t);                   // B3^T -> RT0 (async)
    cpT(sb, RT1_O, g_TW[3], t);                   // B4   -> RT1 (async)
    {   // zero RD (32KB)
        uint4 z = {0,0,0,0};
        uint4* pd = (uint4*)(smc + RD_O);
        for (int i = t; i < 2048; i += 512) pd[i] = z;
    }
    __syncthreads();

    // gather D -> dpack^T in RD: rows kk = k|64+k, cols = m | 33+m
    const size_t base = ((size_t)bimg*512 + ch) * NPOS;
    for (int o = t; o < NPOS; o += 512) {
        int k = o / 33, m = o - k*33;
        float2 df = __half22float2(g_D[base + o]);
        float a = df.x, b = df.y;
        if (m == 0) { a *= 0.5f; b *= 0.5f; }
        wr1(smc, k,      m,      a);
        wr1(smc, k,      33 + m, b);
        wr1(smc, 64 + k, m,      b);
        wr1(smc, 64 + k, 33 + m, -a);
    }
    CP_WAIT(0);
    __syncthreads();

    float c[2][4][4];
    ZERO_C(c);
    if (wn != 3) gemm_ssB(sb, c, lane, wm, wn, 8, RT0_O);   // G^T = B3^T @ dpack^T
    __syncthreads();

    #pragma unroll
    for (int mt = 0; mt < 2; ++mt)
        #pragma unroll
        for (int nt = 0; nt < 4; ++nt) {
            int r0 = wm*32 + mt*16 + g, cb = wn*32 + nt*8 + tq*2;
            wr2(smc, r0,     cb, c[mt][nt][0], c[mt][nt][1]);
            wr2(smc, r0 + 8, cb, c[mt][nt][2], c[mt][nt][3]);
        }
    __syncthreads();

    ZERO_C(c);
    gemm_ssA(sb, c, lane, wm, wn, 5, RT1_O);        // u = G^T @ B4 (K<=80)

    const float* xim = x + (size_t)img * 16384;
    __half* up = g_u + (size_t)img * 16384;
    #pragma unroll
    for (int mt = 0; mt < 2; ++mt)
        #pragma unroll
        for (int nt = 0; nt < 4; ++nt) {
            int r0 = wm*32 + mt*16 + g, cb = wn*32 + nt*8 + tq*2;
            #pragma unroll
            for (int hrow = 0; hrow < 2; ++hrow) {
                int r = r0 + hrow*8;
                float v0 = c[mt][nt][hrow*2 + 0];
                float v1 = c[mt][nt][hrow*2 + 1];
                int o = r*128 + cb;
                float2 xv = *(const float2*)(xim + o);
                float a = fmaf(v0, 0.015625f, xv.x);
                float b = fmaf(v1, 0.015625f, xv.y);
                *(uint32_t*)(up + o) = hp2(a, b);
            }
        }
}

// ---------------------------------------------------------------------------
// K4: HMMA fp16 GEMM: A = fw single, B = u single.  out = x + fw @ u.
// CTA 128x128, 8 warps, K-chunk 32, cp.async 3 stages.
// ---------------------------------------------------------------------------
#define STG_B 16384
#define OFF_A 0
#define OFF_B 8192

__global__ __launch_bounds__(256, 2) void k_gemm_mma(
    const float* __restrict__ x, float* __restrict__ out)
{
    extern __shared__ char smc[];
    const uint32_t sb = smem_u32(smc);
    const int t    = threadIdx.x;
    const int lane = t & 31;
    const int wid  = t >> 5;
    const int wm   = wid >> 1;
    const int wn   = wid & 1;
    const int m0   = blockIdx.x * 128;
    const int n0g  = blockIdx.y * 128;
    const int bimg = n0g >> 14;
    const int s0   = n0g & 16383;

    const char* pA = (const char*)g_fw;
    const char* pB = (const char*)g_u;

    int ar0 = (t + 0)   >> 2, au0 = (t + 0)   & 3;
    int ar1 = (t + 256) >> 2, au1 = (t + 256) & 3;
    uint32_t adst0 = (uint32_t)(ar0*64 + ((au0 ^ ((ar0>>1)&3)) << 4));
    uint32_t adst1 = (uint32_t)(ar1*64 + ((au1 ^ ((ar1>>1)&3)) << 4));
    int br0 = (t + 0)   >> 4, bu0 = (t + 0)   & 15;
    int br1 = (t + 256) >> 4, bu1 = (t + 256) & 15;
    uint32_t bdst0 = (uint32_t)(br0*256 + ((bu0 ^ (br0&7)) << 4));
    uint32_t bdst1 = (uint32_t)(br1*256 + ((bu1 ^ (br1&7)) << 4));

    float c[2][8][4];
    #pragma unroll
    for (int i = 0; i < 2; ++i)
        #pragma unroll
        for (int j = 0; j < 8; ++j) {
            c[i][j][0] = 0.f; c[i][j][1] = 0.f; c[i][j][2] = 0.f; c[i][j][3] = 0.f;
        }

    const int lrow8 = (lane & 7) + 8*((lane >> 3) & 1);
    const int lsel  = lane >> 4;

    #define ISSUE_STAGE(kc, buf) do { \
        uint32_t st_ = sb + (buf)*STG_B; \
        { size_t so = ((size_t)(m0 + ar0)*512 + (kc)*32 + au0*8)*2; \
          CP16(st_ + OFF_A + adst0, pA + so); } \
        { size_t so = ((size_t)(m0 + ar1)*512 + (kc)*32 + au1*8)*2; \
          CP16(st_ + OFF_A + adst1, pA + so); } \
        { size_t so = ((size_t)(bimg*512 + (kc)*32 + br0)*16384 + s0 + bu0*8)*2; \
          CP16(st_ + OFF_B + bdst0, pB + so); } \
        { size_t so = ((size_t)(bimg*512 + (kc)*32 + br1)*16384 + s0 + bu1*8)*2; \
          CP16(st_ + OFF_B + bdst1, pB + so); } \
        CP_COMMIT(); \
    } while (0)

    ISSUE_STAGE(0, 0);
    ISSUE_STAGE(1, 1);
    ISSUE_STAGE(2, 2);

    for (int kc = 0; kc < 16; ++kc) {
        const int buf = kc % 3;
        if (kc < 14)      { CP_WAIT(2); }
        else if (kc == 14){ CP_WAIT(1); }
        else              { CP_WAIT(0); }
        __syncthreads();

        const uint32_t st = sb + buf*STG_B;
        #pragma unroll
        for (int ks = 0; ks < 2; ++ks) {
            uint32_t ah[2][4], bh[4][4];
            #pragma unroll
            for (int mt = 0; mt < 2; ++mt) {
                int row  = wm*32 + mt*16 + lrow8;
                int unit = ks*2 + lsel;
                uint32_t off = (uint32_t)(row*64 + ((unit ^ ((row>>1)&3)) << 4));
                LDSM4(ah[mt], st + OFF_A + off);
            }
            #pragma unroll
            for (int nq = 0; nq < 4; ++nq) {
                int krow = ks*16 + lrow8;
                int unit = wn*8 + nq*2 + lsel;
                uint32_t off = (uint32_t)(krow*256 + ((unit ^ (krow&7)) << 4));
                LDSM4T(bh[nq], st + OFF_B + off);
            }
            #pragma unroll
            for (int mt = 0; mt < 2; ++mt)
                #pragma unroll
                for (int nt = 0; nt < 8; ++nt) {
                    const int nq = nt >> 1, hb = (nt & 1) * 2;
                    MMA_F16(c[mt][nt], ah[mt], bh[nq][hb], bh[nq][hb+1]);
                }
        }
        __syncthreads();
        if (kc + 3 < 16) ISSUE_STAGE(kc + 3, (kc + 3) % 3);
    }

    const int g  = lane >> 2;
    const int tq = lane & 3;
    const size_t obase = (size_t)(bimg * 512);
    #pragma unroll
    for (int mt = 0; mt < 2; ++mt)
        #pragma unroll
        for (int nt = 0; nt < 8; ++nt) {
            int row0 = m0 + wm*32 + mt*16 + g;
            int col  = s0 + wn*64 + nt*8 + tq*2;
            size_t go = (obase + row0)*16384 + col;
            float2 xv = *(const float2*)(x + go);
            float2 ov = { c[mt][nt][0] + xv.x, c[mt][nt][1] + xv.y };
            *(float2*)(out + go) = ov;
            go += (size_t)8 * 16384;
            xv = *(const float2*)(x + go);
            float2 ov2 = { c[mt][nt][2] + xv.x, c[mt][nt][3] + xv.y };
            *(float2*)(out + go) = ov2;
        }
}

// ---------------------------------------------------------------------------
#define SMEM_GMM (3 * STG_B)

extern "C" void kernel_launch(void* const* d_in, const int* in_sizes, int n_in,
                              void* d_out, int out_size)
{
    const float* x   = (const float*)d_in[0];
    const float* w1r = (const float*)d_in[1];
    const float* w1i = (const float*)d_in[2];
    const float* b1r = (const float*)d_in[3];
    const float* b1i = (const float*)d_in[4];
    const float* w2r = (const float*)d_in[5];
    const float* w2i = (const float*)d_in[6];
    const float* b2r = (const float*)d_in[7];
    const float* b2i = (const float*)d_in[8];
    const float* fw  = (const float*)d_in[9];
    float* out = (float*)d_out;

    cudaFuncSetAttribute(k_fwd_mma, cudaFuncAttributeMaxDynamicSharedMemorySize, SMEM_K);
    cudaFuncSetAttribute(k_inv_mma, cudaFuncAttributeMaxDynamicSharedMemorySize, SMEM_K);
    cudaFuncSetAttribute(k_mlp_mma, cudaFuncAttributeMaxDynamicSharedMemorySize, SMEM_K);
    cudaFuncSetAttribute(k_gemm_mma,cudaFuncAttributeMaxDynamicSharedMemorySize, SMEM_GMM);

    k_prep<<<1024, 256>>>(w1r, w1i, w2r, w2i, b1r, b1i, b2r, b2i, fw);

    k_fwd_mma<<<BB*CC, 512, SMEM_K>>>(x);

    dim3 g2((BB*NPOS)/128, NBQ);
    k_mlp_mma<<<g2, 512, SMEM_K>>>();

    k_inv_mma<<<BB*CC, 512, SMEM_K>>>(x);

    dim3 gg(4, BB*16384/128);
    k_gemm_mma<<<gg, 256, SMEM_GMM>>>(x, out);
}